// round 9
// baseline (speedup 1.0000x reference)
#include <cuda_runtime.h>
#include <cuda_bf16.h>
#include <math.h>

#define NPIX    768
#define NP      (NPIX * NPIX)       // 589824
#define NP4     (NP / 4)            // 147456
#define NTERMS  128
#define PPSZ    256
#define NOUT    (PPSZ * PPSZ)       // 65536
#define NBLOCKS 576                 // NP4 / 256, exact
#define NTHR    256

// Scratch for latent^T: L[I][J] = sum_n basis[n, I, J] * coeffs[n]  (2.36 MB)
__device__ float g_latent[NP];

// Barrier state. Monotonic across launches (launches are stream-serialized),
// so no reset is needed and graph replay is safe.
//   g_bar:     arrival ticket counter (each launch adds exactly NBLOCKS)
//   g_release: number of fully-completed epochs (set by last arriver)
// Separate 128B lines so poller reads never contend with arrival RMWs.
__device__ __align__(128) unsigned long long g_bar = 0ULL;
__device__ __align__(128) unsigned long long g_release = 0ULL;

// ---------------------------------------------------------------------------
// Single fused kernel.
// Phase 1 (all 576 blocks): HBM-streaming weighted reduction. Basis loads use
//   __ldcs (evict-first) so the 302MB stream does NOT evict the 2.36MB latent
//   from L2 — phase 2 must hit L2, not DRAM.
// Barrier: arrivals via atomicAdd; LAST arriver publishes g_release; waiters
//   poll g_release with plain ld.global.cg (no atomic-ALU contention).
// Phase 2 (blocks 0..255): one CLIMB patch per thread from L2-resident latent.
// ---------------------------------------------------------------------------
__global__ void __launch_bounds__(NTHR) fused_kernel(
    const float4* __restrict__ basis4,
    const float*  __restrict__ coeffs,
    const float*  __restrict__ wavel_ptr,
    float*        __restrict__ out)
{
    __shared__ float sc[NTERMS];
    __shared__ unsigned long long s_epoch;   // this launch's epoch + 1
    if (threadIdx.x < NTERMS) sc[threadIdx.x] = coeffs[threadIdx.x];
    __syncthreads();

    // ---------------- Phase 1: streaming reduction ----------------
    int idx = blockIdx.x * NTHR + threadIdx.x;   // 0 .. NP4-1 (exact)
    const float4* p = basis4 + idx;
    float4 acc = make_float4(0.f, 0.f, 0.f, 0.f);

#pragma unroll 8
    for (int n = 0; n < NTERMS; n++) {
        float4 v = __ldcs(p + (size_t)n * NP4);   // evict-first: protect latent in L2
        float  c = sc[n];
        acc.x = fmaf(v.x, c, acc.x);
        acc.y = fmaf(v.y, c, acc.y);
        acc.z = fmaf(v.z, c, acc.z);
        acc.w = fmaf(v.w, c, acc.w);
    }
    reinterpret_cast<float4*>(g_latent)[idx] = acc;

    // ---------------- Arrival + release ----------------
    __threadfence();          // latent stores visible before arrival
    __syncthreads();
    if (threadIdx.x == 0) {
        unsigned long long ticket = atomicAdd(&g_bar, 1ULL);
        unsigned long long epoch1 = ticket / NBLOCKS + 1ULL;  // epoch+1
        s_epoch = epoch1;
        if ((ticket % NBLOCKS) == NBLOCKS - 1) {
            atomicMax(&g_release, epoch1);   // last arriver publishes release
        }
    }
    __syncthreads();

    // Blocks with no phase-2 work exit now (their arrival already counted).
    if (blockIdx.x >= NOUT / NTHR) return;

    // ---------------- Wait (read-only polling) ----------------
    if (threadIdx.x == 0) {
        unsigned long long need = s_epoch;
        while (__ldcg(&g_release) < need) {
            __nanosleep(32);
        }
    }
    __syncthreads();
    __threadfence();          // acquire: order release observation before loads

    // ---------------- Phase 2: CLIMB, one patch per thread ----------------
    int o  = blockIdx.x * NTHR + threadIdx.x;    // 0 .. 65535
    int Cb = o >> 8;
    int Rb = o & 255;

    const float* base = g_latent + (3 * Cb) * NPIX + 3 * Rb;

    // Front-batch the 9 independent loads (k = 3r+c maps to base[c*768 + r])
    float z0 = base[0 * NPIX + 0];
    float z1 = base[1 * NPIX + 0];
    float z2 = base[2 * NPIX + 0];
    float z3 = base[0 * NPIX + 1];
    float z4 = base[1 * NPIX + 1];
    float z5 = base[2 * NPIX + 1];
    float z6 = base[0 * NPIX + 2];
    float z7 = base[1 * NPIX + 2];
    float z8 = base[2 * NPIX + 2];

    float zz[9] = {z0, z1, z2, z3, z4, z5, z6, z7, z8};

    // LSQ plane fit over unit 3x3 grid (orthogonal regressors):
    //   a = sum z*(x-1/2)/1.5,  b = sum z*(y-1/2)/1.5,
    //   c = mean(z) - a/2 - b/2
    float S = 0.f, Sx = 0.f, Sy = 0.f;
    bool allpos = true, allnonpos = true, anyzero = false;
#pragma unroll
    for (int k = 0; k < 9; k++) {
        float v  = zz[k];
        float xk = 0.5f * (float)(k % 3);
        float yk = 0.5f * (float)(k / 3);
        S  += v;
        Sx += v * xk;
        Sy += v * yk;
        allpos    = allpos    && (v > 0.f);
        allnonpos = allnonpos && (v <= 0.f);
        anyzero   = anyzero   || (v == 0.f);
    }
    float mean = S * (1.f / 9.f);
    float a  = (Sx - 0.5f * S) * (1.f / 1.5f);
    float b  = (Sy - 0.5f * S) * (1.f / 1.5f);
    float cc = mean - 0.5f * a - 0.5f * b;

    const float EPSF = 1e-15f;
    if (a  == 0.f) a  = EPSF;
    if (b  == 0.f) b  = EPSF;
    if (cc == 0.f) cc = EPSF;

    float x1 = (-b - cc) / a;
    float x2 = (-cc) / a;
    float lo = fminf(x1, x2);
    float hi = fmaxf(x1, x2);
    x1 = fmaxf(lo, 0.f);
    x2 = fminf(hi, 1.f);

    float ncb = (-cc) / b;
    float ab  = a / b;
    float d = x1 + ncb * x2 - 0.5f * ab * x2 * x2
                 - ncb * x1 + 0.5f * ab * x1 * x1;

    d = (d >= 0.5f)   ? d : (1.0f - d);
    d = (mean >= 0.f) ? d : (1.0f - d);
    if (allpos)    d = 1.0f;
    if (allnonpos) d = 0.0f;
    if (anyzero)   d = (d > 0.f) ? 1.0f : 0.0f;
    d = fminf(fmaxf(d, 0.f), 1.f);

    // opd = pi*d * wavel / (2*pi)
    float wl = *wavel_ptr;
    out[o] = ((float)M_PI * d) * wl * (1.0f / (2.0f * (float)M_PI));
}

extern "C" void kernel_launch(void* const* d_in, const int* in_sizes, int n_in,
                              void* d_out, int out_size)
{
    const float4* basis4 = reinterpret_cast<const float4*>(d_in[0]); // (128,768,768) f32
    const float*  coeffs = reinterpret_cast<const float*>(d_in[1]);  // (128,)
    const float*  wavel  = reinterpret_cast<const float*>(d_in[2]);  // scalar
    float*        out    = reinterpret_cast<float*>(d_out);          // (256,256) f32

    (void)in_sizes; (void)n_in; (void)out_size;

    fused_kernel<<<NBLOCKS, NTHR>>>(basis4, coeffs, wavel, out);
}

// round 10
// speedup vs baseline: 1.0345x; 1.0345x over previous
#include <cuda_runtime.h>
#include <cuda_bf16.h>
#include <math.h>

#define NPIX     768
#define NP       (NPIX * NPIX)     // 589824 floats per basis term
#define NP4      (NP / 4)          // 147456 float4 per basis term
#define ROW4     (NPIX / 4)        // 192 float4 per row
#define NTERMS   128
#define PPSZ     256
#define THREADS  288               // 3 rows x 96 float4 = 288 float4 per region
#define HALFJ4   96                // 384 floats / 4

// ---------------------------------------------------------------------------
// Fully fused, block-local kernel. Each of 512 blocks streams basis rows
// I in [3*Cb, 3*Cb+3), columns J in [Jhalf*384, Jhalf*384+384), reduces over
// the 128 terms in registers, stages the 3x384 latent band in SHARED memory,
// and computes its 128 CLIMB patches locally. No global latent array, no
// grid barrier, no second launch: patches are disjoint 3x3 tiles, so all
// data dependencies are block-local. Plain loads (NOT __ldcs — evict-first
// measurably costs ~12% streaming bandwidth on GB300).
// ---------------------------------------------------------------------------
__global__ void __launch_bounds__(THREADS) fused_climb_kernel(
    const float4* __restrict__ basis4,
    const float*  __restrict__ coeffs,
    const float*  __restrict__ wavel_ptr,
    float*        __restrict__ out)
{
    __shared__ float sc[NTERMS];
    __shared__ float tile[3][384];   // latent band: tile[c][localJ]

    int t = threadIdx.x;
    if (t < NTERMS) sc[t] = coeffs[t];
    __syncthreads();

    int Cb    = blockIdx.x >> 1;     // 0..255
    int Jhalf = blockIdx.x & 1;      // 0..1

    // This thread's float4 slot within the 3x384 region
    int row  = t / HALFJ4;           // 0..2  (c index / I-row within band)
    int col4 = t % HALFJ4;           // 0..95

    const float4* p = basis4
        + (size_t)(3 * Cb + row) * ROW4
        + (size_t)Jhalf * HALFJ4
        + col4;

    float4 acc = make_float4(0.f, 0.f, 0.f, 0.f);

#pragma unroll 8
    for (int n = 0; n < NTERMS; n++) {
        float4 v = p[(size_t)n * NP4];       // plain load — keep full stream BW
        float  c = sc[n];
        acc.x = fmaf(v.x, c, acc.x);
        acc.y = fmaf(v.y, c, acc.y);
        acc.z = fmaf(v.z, c, acc.z);
        acc.w = fmaf(v.w, c, acc.w);
    }

    // Stage latent band in shared memory
    *reinterpret_cast<float4*>(&tile[row][col4 * 4]) = acc;
    __syncthreads();

    // ---- CLIMB patch compute: threads 0..127 each handle one patch ----
    if (t < 128) {
        int pch = t;                         // local patch index (J direction)
        // z[3r+c] = latent[I = 3Cb+c, J = Jbase + 3*pch + r] = tile[c][3*pch+r]
        float z[9];
#pragma unroll
        for (int c = 0; c < 3; c++) {
#pragma unroll
            for (int r = 0; r < 3; r++) {
                z[3 * r + c] = tile[c][3 * pch + r];
            }
        }

        // LSQ plane fit over unit 3x3 grid (orthogonal regressors):
        //   a = sum z*(x-1/2)/1.5,  b = sum z*(y-1/2)/1.5,
        //   cc = mean(z) - a/2 - b/2
        float S = 0.f, Sx = 0.f, Sy = 0.f;
        bool allpos = true, allnonpos = true, anyzero = false;
#pragma unroll
        for (int k = 0; k < 9; k++) {
            float v  = z[k];
            float xk = 0.5f * (float)(k % 3);
            float yk = 0.5f * (float)(k / 3);
            S  += v;
            Sx += v * xk;
            Sy += v * yk;
            allpos    = allpos    && (v > 0.f);
            allnonpos = allnonpos && (v <= 0.f);
            anyzero   = anyzero   || (v == 0.f);
        }
        float mean = S * (1.f / 9.f);
        float a  = (Sx - 0.5f * S) * (1.f / 1.5f);
        float b  = (Sy - 0.5f * S) * (1.f / 1.5f);
        float cc = mean - 0.5f * a - 0.5f * b;

        const float EPSF = 1e-15f;
        if (a  == 0.f) a  = EPSF;
        if (b  == 0.f) b  = EPSF;
        if (cc == 0.f) cc = EPSF;

        float x1 = (-b - cc) / a;
        float x2 = (-cc) / a;
        float lo = fminf(x1, x2);
        float hi = fmaxf(x1, x2);
        x1 = fmaxf(lo, 0.f);
        x2 = fminf(hi, 1.f);

        float ncb = (-cc) / b;
        float ab  = a / b;
        float d = x1 + ncb * x2 - 0.5f * ab * x2 * x2
                     - ncb * x1 + 0.5f * ab * x1 * x1;

        d = (d >= 0.5f)   ? d : (1.0f - d);
        d = (mean >= 0.f) ? d : (1.0f - d);
        if (allpos)    d = 1.0f;
        if (allnonpos) d = 0.0f;
        if (anyzero)   d = (d > 0.f) ? 1.0f : 0.0f;
        d = fminf(fmaxf(d, 0.f), 1.f);

        // opd = pi*d * wavel / (2*pi)
        float wl = *wavel_ptr;
        int Rb = Jhalf * 128 + pch;
        out[Cb * PPSZ + Rb] = ((float)M_PI * d) * wl * (1.0f / (2.0f * (float)M_PI));
    }
}

extern "C" void kernel_launch(void* const* d_in, const int* in_sizes, int n_in,
                              void* d_out, int out_size)
{
    const float4* basis4 = reinterpret_cast<const float4*>(d_in[0]); // (128,768,768) f32
    const float*  coeffs = reinterpret_cast<const float*>(d_in[1]);  // (128,)
    const float*  wavel  = reinterpret_cast<const float*>(d_in[2]);  // scalar
    float*        out    = reinterpret_cast<float*>(d_out);          // (256,256) f32

    (void)in_sizes; (void)n_in; (void)out_size;

    fused_climb_kernel<<<512, THREADS>>>(basis4, coeffs, wavel, out);
}